// round 8
// baseline (speedup 1.0000x reference)
#include <cuda_runtime.h>
#include <math_constants.h>

#define BATCH    8
#define NSHAPE   8192
#define NSKEL    2048
#define SSTRIDE  6

#define NB       256
#define XMIN     (-6.0f)
#define INVSTEP  21.3333333f     /* 256 bins over [-6,6] */

#define QG       256             /* queries per group */
#define G1       (BATCH * NSHAPE / QG)   /* 256 */
#define G2       (BATCH * NSKEL  / QG)   /* 64  */
#define NG       (G1 + G2)               /* 320 */

#define NESK     (NSKEL  / 2)    /* 1024 packed entries */
#define NESH     (NSHAPE / 2)    /* 4096 */

#define AW_E     128             /* bound-pass rank window: 128 entries = 256 pts */
#define CH_E     64              /* scan chunk: 64 entries = 128 pts */
#define MAXCH1   16              /* 1024/64 : side1 candidate chunks  */
#define MAXCH2   64              /* 4096/64 : side2 candidate chunks  */
#define K3B      (G1 * MAXCH1 + G2 * MAXCH2)  /* 8192 */

// Sorted clouds: per-point float4 (x,y,z,|p|^2) + packed pair entries
// (A=(x0,x1,y0,y1), B=(z0,z1,n0,n1)) + 256-bin x CDF. Rewritten every call by
// prep/bound; key/counter state zero-init and self-resetting => graph-safe.
__device__ float4 g_q4Sh[BATCH][NSHAPE];
__device__ float4 g_q4Sk[BATCH][NSKEL];
__device__ float4 g_pASh[BATCH][NESH], g_pBSh[BATCH][NESH];
__device__ float4 g_pASk[BATCH][NESK], g_pBSk[BATCH][NESK];
__device__ unsigned int g_cdfSh[BATCH][NB + 1];
__device__ unsigned int g_cdfSk[BATCH][NB + 1];
__device__ unsigned int g_e0[NG];
__device__ unsigned int g_nch[NG];
__device__ unsigned int g_key[NG * QG];   // ~bits(min d2); 0 = identity
__device__ unsigned int g_gc[NG];
__device__ unsigned int g_done;
__device__ float        g_accum;

// ---------------------------------------------------------------------------
__device__ __forceinline__ int xbin(float x) {
    int b = (int)floorf((x - XMIN) * INVSTEP);
    return min(max(b, 0), NB - 1);
}
__device__ __forceinline__ unsigned long long pack2(float v) {
    unsigned long long r;
    asm("mov.b64 %0, {%1,%2};" : "=l"(r) : "f"(v), "f"(v));
    return r;
}
__device__ __forceinline__ unsigned long long fma2(unsigned long long a,
                                                   unsigned long long b,
                                                   unsigned long long c) {
    unsigned long long d;
    asm("fma.rn.f32x2 %0, %1, %2, %3;" : "=l"(d) : "l"(a), "l"(b), "l"(c));
    return d;
}
__device__ __forceinline__ void unpack2(unsigned long long v, float& lo, float& hi) {
    asm("mov.b64 {%0,%1}, %2;" : "=f"(lo), "=f"(hi) : "l"(v));
}
__device__ __forceinline__ float block_reduce_sum(float v) {
    __shared__ float ws[4];
    const int lane = threadIdx.x & 31, wid = threadIdx.x >> 5;
#pragma unroll
    for (int o = 16; o > 0; o >>= 1) v += __shfl_down_sync(0xffffffffu, v, o);
    if (lane == 0) ws[wid] = v;
    __syncthreads();
    if (wid == 0) {
        v = (lane < 4) ? ws[lane] : 0.0f;
#pragma unroll
        for (int o = 2; o > 0; o >>= 1) v += __shfl_down_sync(0xffffffffu, v, o);
    }
    return v;
}
__device__ __forceinline__ float block_reduce_max_bcast(float v) {
    __shared__ float ws[4];
    const int lane = threadIdx.x & 31, wid = threadIdx.x >> 5;
#pragma unroll
    for (int o = 16; o > 0; o >>= 1) v = fmaxf(v, __shfl_xor_sync(0xffffffffu, v, o));
    if (lane == 0) ws[wid] = v;
    __syncthreads();
    return fmaxf(fmaxf(ws[0], ws[1]), fmaxf(ws[2], ws[3]));
}

// hot loop: n packed entries, 2 queries; t_j = n_j - 2 q.p_j
__device__ __forceinline__ void scan_entries(
    const float4* __restrict__ sA, const float4* __restrict__ sB, int n,
    unsigned long long cx0, unsigned long long cy0, unsigned long long cz0,
    unsigned long long cx1, unsigned long long cy1, unsigned long long cz1,
    float& m0, float& m1)
{
    const ulonglong2* pA = reinterpret_cast<const ulonglong2*>(sA);
    const ulonglong2* pB = reinterpret_cast<const ulonglong2*>(sB);
#pragma unroll 4
    for (int jj = 0; jj < n; jj++) {
        const ulonglong2 A = pA[jj];   // (x-pair, y-pair)
        const ulonglong2 B = pB[jj];   // (z-pair, n-pair)
        unsigned long long t0 = fma2(cx0, A.x, B.y);
        t0 = fma2(cy0, A.y, t0);
        t0 = fma2(cz0, B.x, t0);
        unsigned long long t1 = fma2(cx1, A.x, B.y);
        t1 = fma2(cy1, A.y, t1);
        t1 = fma2(cz1, B.x, t1);
        float lo, hi;
        unpack2(t0, lo, hi); m0 = fminf(m0, fminf(lo, hi));
        unpack2(t1, lo, hi); m1 = fminf(m1, fminf(lo, hi));
    }
}

// ---------------------------------------------------------------------------
// Prep: deterministic counting sort by x-bin per (array,batch); 16 blocks.
// Writes sorted q4 (x,y,z,n), packed pair arrays, and the bin CDF.
// ---------------------------------------------------------------------------
__global__ void __launch_bounds__(256) prep_kernel(
    const float* __restrict__ shape, const float* __restrict__ skel)
{
    __shared__ unsigned int sBR[NSHAPE];       // bin<<16 | intra-warp rank
    __shared__ unsigned int wHist[8][NB];
    __shared__ unsigned int sScan[NB];
    __shared__ unsigned int sCdf[NB + 1];

    const int tid  = threadIdx.x;
    const int w    = tid >> 5;
    const int lane = tid & 31;
    const bool isShape = (blockIdx.x < 8);
    const int b      = isShape ? blockIdx.x : blockIdx.x - 8;
    const int N      = isShape ? NSHAPE : NSKEL;
    const int stride = isShape ? 6 : 3;
    const int lgch   = isShape ? 10 : 8;       // log2(N/8)
    const float* src = isShape ? shape + (size_t)b * NSHAPE * 6
                               : skel  + (size_t)b * NSKEL * 3;

    for (int i = tid; i < 8 * NB; i += 256) ((unsigned int*)wHist)[i] = 0;
    __syncthreads();

    const int chunk = N >> 3;
    const int base  = w * chunk;
    for (int s = 0; s < chunk / 32; s++) {
        const int i = base + s * 32 + lane;
        const float x = src[i * stride];
        const int bn = xbin(x);
        const unsigned mask  = __match_any_sync(0xffffffffu, bn);
        const unsigned lower = __popc(mask & ((1u << lane) - 1u));
        const unsigned prev  = wHist[w][bn];
        __syncwarp();
        sBR[i] = ((unsigned)bn << 16) | (prev + lower);
        if (lower == 0) wHist[w][bn] = prev + __popc(mask);
        __syncwarp();
    }
    __syncthreads();

    if (tid < NB) {
        unsigned run = 0;
#pragma unroll
        for (int ww = 0; ww < 8; ww++) {
            const unsigned c = wHist[ww][tid];
            wHist[ww][tid] = run;
            run += c;
        }
        sScan[tid] = run;
    }
    __syncthreads();
    for (int off = 1; off < NB; off <<= 1) {    // inclusive Hillis-Steele
        unsigned v = 0;
        if (tid < NB && tid >= off) v = sScan[tid - off];
        __syncthreads();
        if (tid < NB) sScan[tid] += v;
        __syncthreads();
    }
    if (tid < NB) sCdf[tid + 1] = sScan[tid];
    if (tid == 0) sCdf[0] = 0;
    __syncthreads();

    float4* q4 = isShape ? g_q4Sh[b] : g_q4Sk[b];
    for (int i = tid; i < N; i += 256) {
        const unsigned br = sBR[i];
        const int bn = br >> 16;
        const unsigned r = sCdf[bn] + wHist[i >> lgch][bn] + (br & 0xffffu);
        const float* p = src + i * stride;
        const float x = p[0], y = p[1], z = p[2];
        q4[r] = make_float4(x, y, z, fmaf(x, x, fmaf(y, y, z * z)));
    }
    unsigned int* gcdf = isShape ? g_cdfSh[b] : g_cdfSk[b];
    if (tid <= NB) gcdf[tid] = sCdf[tid];
    __syncthreads();   // block-scope visibility of q4 global writes

    // build packed-pair candidate layout from sorted q4
    float4* pA = isShape ? g_pASh[b] : g_pASk[b];
    float4* pB = isShape ? g_pBSh[b] : g_pBSk[b];
    for (int e = tid; e < (N >> 1); e += 256) {
        const float4 p0 = q4[2 * e], p1 = q4[2 * e + 1];
        pA[e] = make_float4(p0.x, p1.x, p0.y, p1.y);
        pB[e] = make_float4(p0.z, p1.z, p0.w, p1.w);
    }
}

// ---------------------------------------------------------------------------
// Bound kernel: one block per query group. Dense scan of a 256-point rank
// window -> per-query upper bound (seeds g_key) -> block-max radius -> exact
// candidate entry window [e0,e1) via CDF -> header {e0, nch}.
// ---------------------------------------------------------------------------
__global__ void __launch_bounds__(128) bound_kernel()
{
    __shared__ float4 sA[AW_E];
    __shared__ float4 sB[AW_E];

    const int tid = threadIdx.x;
    const int gid = blockIdx.x;
    const bool side1 = (gid < G1);

    const float4 *q4, *pA, *pB;
    const unsigned int* cdf;
    int NE, qbase;
    if (side1) {                     // queries = sorted shape, cand = skel
        const int b = gid >> 5;
        qbase = (gid & 31) * QG;
        q4 = g_q4Sh[b]; pA = g_pASk[b]; pB = g_pBSk[b];
        cdf = g_cdfSk[b]; NE = NESK;
    } else {                         // queries = sorted skel, cand = shape
        const int r = gid - G1;
        const int b = r >> 3;
        qbase = (r & 7) * QG;
        q4 = g_q4Sk[b]; pA = g_pASh[b]; pB = g_pBSh[b];
        cdf = g_cdfSh[b]; NE = NESH;
    }

    const float4 q0 = q4[qbase + tid];
    const float4 q1 = q4[qbase + 128 + tid];
    const float xlo = q4[qbase].x;              // sorted: group extents
    const float xhi = q4[qbase + QG - 1].x;

    // rank window centered on group's x-mid
    const int c  = (int)cdf[xbin(0.5f * (xlo + xhi))];
    const int a0 = min(max((c >> 1) - (AW_E >> 1), 0), NE - AW_E);
    sA[tid] = pA[a0 + tid];
    sB[tid] = pB[a0 + tid];
    __syncthreads();

    const unsigned long long cx0 = pack2(-2.0f * q0.x), cy0 = pack2(-2.0f * q0.y), cz0 = pack2(-2.0f * q0.z);
    const unsigned long long cx1 = pack2(-2.0f * q1.x), cy1 = pack2(-2.0f * q1.y), cz1 = pack2(-2.0f * q1.z);
    float m0 = CUDART_INF_F, m1 = CUDART_INF_F;
    scan_entries(sA, sB, AW_E, cx0, cy0, cz0, cx1, cy1, cz1, m0, m1);

    const float d2_0 = fmaxf(q0.w + m0, 0.0f);
    const float d2_1 = fmaxf(q1.w + m1, 0.0f);

    // seed keys (no concurrency with scan kernel: separate launch)
    g_key[gid * QG + tid]       = 0xFFFFFFFFu ^ __float_as_uint(d2_0);
    g_key[gid * QG + tid + 128] = 0xFFFFFFFFu ^ __float_as_uint(d2_1);

    const float rad  = fmaxf(sqrtf(d2_0), sqrtf(d2_1)) * 1.0001f;
    const float rmax = block_reduce_max_bcast(rad);

    if (tid == 0) {
        const int p0 = (int)cdf[xbin(xlo - rmax)];
        const int p1 = (int)cdf[xbin(xhi + rmax) + 1];
        const int e0 = p0 >> 1;
        const int e1 = min((p1 + 1) >> 1, NE);
        g_e0[gid]  = (unsigned)e0;
        g_nch[gid] = (unsigned)max(1, (e1 - e0 + CH_E - 1) / CH_E);
    }
}

// ---------------------------------------------------------------------------
// Scan kernel: block = (group, chunk); early-exit when chunk >= nch.
// Scans CH_E entries of the group's window; merges minima via atomicMax on
// ~bits keys; last chunk finalizes (sqrt+sum, resets state for next replay).
// ---------------------------------------------------------------------------
__global__ void __launch_bounds__(128) scan_kernel(float* __restrict__ out)
{
    __shared__ float4 sA[CH_E];
    __shared__ float4 sB[CH_E];
    __shared__ unsigned int sLast;

    const int tid = threadIdx.x;
    const int bid = blockIdx.x;

    int gid, ch;
    const float4 *q4, *pA, *pB;
    int NE, qbase;
    if (bid < G1 * MAXCH1) {
        gid = bid >> 4; ch = bid & 15;
        const int b = gid >> 5;
        qbase = (gid & 31) * QG;
        q4 = g_q4Sh[b]; pA = g_pASk[b]; pB = g_pBSk[b]; NE = NESK;
    } else {
        const int t = bid - G1 * MAXCH1;
        const int r = t >> 6; ch = t & 63;
        gid = G1 + r;
        const int b = r >> 3;
        qbase = (r & 7) * QG;
        q4 = g_q4Sk[b]; pA = g_pASh[b]; pB = g_pBSh[b]; NE = NESH;
    }

    const int nch = (int)g_nch[gid];
    if (ch >= nch) return;                     // pruned: no work
    const int e0 = (int)g_e0[gid];

    const int js = min(e0 + ch * CH_E, NE);
    const int je = min(js + CH_E, NE);
    const int n  = je - js;

    // tile load: threads 0..63 -> A, 64..127 -> B
    if (tid < CH_E) { if (tid < n) sA[tid] = pA[js + tid]; }
    else            { const int i = tid - CH_E; if (i < n) sB[i] = pB[js + i]; }

    const float4 q0 = q4[qbase + tid];
    const float4 q1 = q4[qbase + 128 + tid];
    const unsigned long long cx0 = pack2(-2.0f * q0.x), cy0 = pack2(-2.0f * q0.y), cz0 = pack2(-2.0f * q0.z);
    const unsigned long long cx1 = pack2(-2.0f * q1.x), cy1 = pack2(-2.0f * q1.y), cz1 = pack2(-2.0f * q1.z);
    __syncthreads();

    float m0 = CUDART_INF_F, m1 = CUDART_INF_F;
    scan_entries(sA, sB, n, cx0, cy0, cz0, cx1, cy1, cz1, m0, m1);

    const float d2_0 = fmaxf(q0.w + m0, 0.0f);
    const float d2_1 = fmaxf(q1.w + m1, 0.0f);
    atomicMax(&g_key[gid * QG + tid],       0xFFFFFFFFu ^ __float_as_uint(d2_0));
    atomicMax(&g_key[gid * QG + tid + 128], 0xFFFFFFFFu ^ __float_as_uint(d2_1));

    // group completion
    __threadfence();
    __syncthreads();
    if (tid == 0) sLast = (atomicAdd(&g_gc[gid], 1u) == (unsigned)(nch - 1));
    __syncthreads();
    if (!sLast) return;
    __threadfence();

    // finalize: read+reset keys, sqrt, sum
    const unsigned int k0 = atomicExch(&g_key[gid * QG + tid], 0u);
    const unsigned int k1 = atomicExch(&g_key[gid * QG + tid + 128], 0u);
    float s = sqrtf(__uint_as_float(0xFFFFFFFFu ^ k0))
            + sqrtf(__uint_as_float(0xFFFFFFFFu ^ k1));
    s = block_reduce_sum(s);

    if (tid == 0) {
        g_gc[gid] = 0;
        atomicAdd(&g_accum, s);
        __threadfence();
        if (atomicAdd(&g_done, 1u) == NG - 1) {
            out[0] = atomicExch(&g_accum, 0.0f) * 1.0e-4f;
            g_done = 0;
        }
    }
}

// ---------------------------------------------------------------------------
extern "C" void kernel_launch(void* const* d_in, const int* in_sizes, int n_in,
                              void* d_out, int out_size)
{
    const float* shape = (const float*)d_in[0];  // (8, 8192, 6) fp32
    const float* skel  = (const float*)d_in[1];  // (8, 2048, 3) fp32
    prep_kernel<<<16, 256>>>(shape, skel);
    bound_kernel<<<NG, 128>>>();
    scan_kernel<<<K3B, 128>>>((float*)d_out);
}